// round 2
// baseline (speedup 1.0000x reference)
#include <cuda_runtime.h>

#define D_MODEL 1024
#define BM 128
#define BN 128
#define BK 8
#define TM 8
#define TN 8
#define MAX_ROWS 16384

// Ping-pong scratch (allocation-free rule: __device__ globals)
__device__ float g_buf0[MAX_ROWS * D_MODEL];
__device__ float g_buf1[MAX_ROWS * D_MODEL];

// ---------------- packed fp32x2 helpers (Blackwell FFMA2 path) ----------------
__device__ __forceinline__ unsigned long long ffma2(unsigned long long a,
                                                    unsigned long long b,
                                                    unsigned long long c) {
    unsigned long long d;
    asm("fma.rn.f32x2 %0, %1, %2, %3;" : "=l"(d) : "l"(a), "l"(b), "l"(c));
    return d;
}
__device__ __forceinline__ unsigned long long pack2(float lo, float hi) {
    unsigned long long r;
    asm("mov.b64 %0, {%1, %2};" : "=l"(r) : "f"(lo), "f"(hi));
    return r;
}
__device__ __forceinline__ float2 unpack2(unsigned long long v) {
    float lo, hi;
    asm("mov.b64 {%0, %1}, %2;" : "=f"(lo), "=f"(hi) : "l"(v));
    return make_float2(lo, hi);
}

__device__ __forceinline__ float silu(float x) {
    return x * (1.0f / (1.0f + __expf(-x)));
}

// ---------------- GEMM: C[M,N] = A[M,K] @ B[K,N] + bias, optional SiLU ----------------
// A row-major, B row-major (weights are (d_in, d_out) per the einsum "bsd,de->bse").
// 256 threads, 128x128 tile, 8x8 per thread, accumulators as f32x2 pairs.
template <int ACT>  // 0 = none, 1 = silu
__global__ __launch_bounds__(256)
void gemm_bias_act(const float* __restrict__ A, const float* __restrict__ B,
                   const float* __restrict__ bias, float* __restrict__ C,
                   int M, int N, int K) {
    __shared__ float As[BK][BM];   // transposed A tile
    __shared__ float Bs[BK][BN];

    const int tid = threadIdx.x;
    const int tx = tid & 15;       // 0..15 -> column group
    const int ty = tid >> 4;       // 0..15 -> row group
    const int bm = blockIdx.y * BM;
    const int bn = blockIdx.x * BN;

    // A tile load: 128 rows x 8 cols, 2 threads per row (float4 each)
    const int arow = tid >> 1;
    const int acol = (tid & 1) * 4;
    // B tile load: 8 rows x 128 cols, 32 threads per row (float4 each)
    const int brow = tid >> 5;
    const int bcol = (tid & 31) * 4;

    const float* Aptr = A + (size_t)(bm + arow) * K + acol;
    const float* Bptr = B + (size_t)brow * N + bn + bcol;

    unsigned long long acc[TM][TN / 2];
#pragma unroll
    for (int i = 0; i < TM; i++)
#pragma unroll
        for (int j = 0; j < TN / 2; j++) acc[i][j] = 0ull;

    for (int k0 = 0; k0 < K; k0 += BK) {
        const float4 av = *(const float4*)(Aptr + k0);
        const float4 bv = *(const float4*)(Bptr + (size_t)k0 * N);
        __syncthreads();   // previous tile's compute done before overwrite
        As[acol + 0][arow] = av.x;
        As[acol + 1][arow] = av.y;
        As[acol + 2][arow] = av.z;
        As[acol + 3][arow] = av.w;
        *(float4*)&Bs[brow][bcol] = bv;
        __syncthreads();

#pragma unroll
        for (int k = 0; k < BK; k++) {
            const float4 a0 = *(const float4*)&As[k][ty * TM];
            const float4 a1 = *(const float4*)&As[k][ty * TM + 4];
            const ulonglong2 bp0 = *(const ulonglong2*)&Bs[k][tx * TN];
            const ulonglong2 bp1 = *(const ulonglong2*)&Bs[k][tx * TN + 4];

            unsigned long long ad[TM];
            ad[0] = pack2(a0.x, a0.x);
            ad[1] = pack2(a0.y, a0.y);
            ad[2] = pack2(a0.z, a0.z);
            ad[3] = pack2(a0.w, a0.w);
            ad[4] = pack2(a1.x, a1.x);
            ad[5] = pack2(a1.y, a1.y);
            ad[6] = pack2(a1.z, a1.z);
            ad[7] = pack2(a1.w, a1.w);
#pragma unroll
            for (int i = 0; i < TM; i++) {
                acc[i][0] = ffma2(ad[i], bp0.x, acc[i][0]);
                acc[i][1] = ffma2(ad[i], bp0.y, acc[i][1]);
                acc[i][2] = ffma2(ad[i], bp1.x, acc[i][2]);
                acc[i][3] = ffma2(ad[i], bp1.y, acc[i][3]);
            }
        }
    }

    // Epilogue: bias (+ optional SiLU), vectorized stores
    const int col = bn + tx * TN;
    const float4 bias0 = *(const float4*)&bias[col];
    const float4 bias1 = *(const float4*)&bias[col + 4];

#pragma unroll
    for (int i = 0; i < TM; i++) {
        const int row = bm + ty * TM + i;
        float2 v0 = unpack2(acc[i][0]);
        float2 v1 = unpack2(acc[i][1]);
        float2 v2 = unpack2(acc[i][2]);
        float2 v3 = unpack2(acc[i][3]);
        float4 o0 = make_float4(v0.x + bias0.x, v0.y + bias0.y,
                                v1.x + bias0.z, v1.y + bias0.w);
        float4 o1 = make_float4(v2.x + bias1.x, v2.y + bias1.y,
                                v3.x + bias1.z, v3.y + bias1.w);
        if (ACT == 1) {
            o0.x = silu(o0.x); o0.y = silu(o0.y); o0.z = silu(o0.z); o0.w = silu(o0.w);
            o1.x = silu(o1.x); o1.y = silu(o1.y); o1.z = silu(o1.z); o1.w = silu(o1.w);
        }
        float* crow = C + (size_t)row * N + col;
        *(float4*)crow = o0;
        *(float4*)(crow + 4) = o1;
    }
}

// ---------------- LayerNorm over last dim (D=1024), eps=1e-5, no scale/bias ----------------
__global__ __launch_bounds__(256)
void layernorm_kernel(const float* __restrict__ in, float* __restrict__ out) {
    __shared__ float2 red[8];
    const int row = blockIdx.x;
    const int tid = threadIdx.x;

    const float4 v = *(const float4*)(in + (size_t)row * D_MODEL + tid * 4);
    float s  = v.x + v.y + v.z + v.w;
    float ss = v.x * v.x + v.y * v.y + v.z * v.z + v.w * v.w;

#pragma unroll
    for (int o = 16; o > 0; o >>= 1) {
        s  += __shfl_xor_sync(0xFFFFFFFFu, s,  o);
        ss += __shfl_xor_sync(0xFFFFFFFFu, ss, o);
    }
    if ((tid & 31) == 0) red[tid >> 5] = make_float2(s, ss);
    __syncthreads();
    if (tid < 32) {
        float2 r = (tid < 8) ? red[tid] : make_float2(0.0f, 0.0f);
        s = r.x; ss = r.y;
#pragma unroll
        for (int o = 4; o > 0; o >>= 1) {
            s  += __shfl_xor_sync(0xFFFFFFFFu, s,  o);
            ss += __shfl_xor_sync(0xFFFFFFFFu, ss, o);
        }
        if (tid == 0) red[0] = make_float2(s, ss);
    }
    __syncthreads();

    const float inv_d = 1.0f / (float)D_MODEL;
    const float mu  = red[0].x * inv_d;
    const float var = red[0].y * inv_d - mu * mu;
    const float r   = rsqrtf(var + 1e-5f);

    float4 o4 = make_float4((v.x - mu) * r, (v.y - mu) * r,
                            (v.z - mu) * r, (v.w - mu) * r);
    *(float4*)(out + (size_t)row * D_MODEL + tid * 4) = o4;
}

// ---------------- launch ----------------
extern "C" void kernel_launch(void* const* d_in, const int* in_sizes, int n_in,
                              void* d_out, int out_size) {
    const float* x     = (const float*)d_in[0];
    const float* wq    = (const float*)d_in[1];
    const float* bq    = (const float*)d_in[2];
    const float* mlp_w = (const float*)d_in[3];
    const float* mlp_b = (const float*)d_in[4];
    const float* w_out = (const float*)d_in[5];
    const float* b_out = (const float*)d_in[6];
    float* out = (float*)d_out;

    const int M = in_sizes[0] / D_MODEL;   // 16384
    const int N = D_MODEL, K = D_MODEL;
    const size_t DD = (size_t)D_MODEL * D_MODEL;

    float *buf0, *buf1;
    cudaGetSymbolAddress((void**)&buf0, g_buf0);
    cudaGetSymbolAddress((void**)&buf1, g_buf1);

    dim3 grid(N / BN, M / BM);
    dim3 block(256);

    // q = x @ wq + bq
    gemm_bias_act<0><<<grid, block>>>(x, wq, bq, buf0, M, N, K);
    // q_norm = LN(q)
    layernorm_kernel<<<M, 256>>>(buf0, buf1);
    // memory MLP: 3x (GEMM + SiLU), then final GEMM (no act)
    gemm_bias_act<1><<<grid, block>>>(buf1, mlp_w + 0 * DD, mlp_b + 0 * D_MODEL, buf0, M, N, K);
    gemm_bias_act<1><<<grid, block>>>(buf0, mlp_w + 1 * DD, mlp_b + 1 * D_MODEL, buf1, M, N, K);
    gemm_bias_act<1><<<grid, block>>>(buf1, mlp_w + 2 * DD, mlp_b + 2 * D_MODEL, buf0, M, N, K);
    gemm_bias_act<0><<<grid, block>>>(buf0, mlp_w + 3 * DD, mlp_b + 3 * D_MODEL, buf1, M, N, K);
    // straight-through adds exactly 0 in the forward pass -> out = h @ w_out + b_out
    gemm_bias_act<0><<<grid, block>>>(buf1, w_out, b_out, out, M, N, K);
}

// round 4
// speedup vs baseline: 2.5654x; 2.5654x over previous
#include <cuda_runtime.h>
#include <cuda_bf16.h>
#include <cstdint>

#define D 1024
#define MAXR 16384
#define DD (D * D)
#define NV 96            // virtual K chunks: 3 planes x 32 real chunks of 32

// ---------------- device scratch (allocation-free rule) ----------------
__device__ __align__(256) __nv_bfloat16 g_ah[MAXR * D], g_al[MAXR * D];
__device__ __align__(256) __nv_bfloat16 g_bh[MAXR * D], g_bl[MAXR * D];
__device__ __align__(256) float g_q[MAXR * D];
__device__ __align__(256) __nv_bfloat16 g_wh[6 * DD], g_wl[6 * DD];

__device__ __forceinline__ void split2(float a, float b, uint32_t& h, uint32_t& l) {
    __nv_bfloat162 hh = __floats2bfloat162_rn(a, b);
    float2 hf = __bfloat1622float2(hh);
    __nv_bfloat162 ll = __floats2bfloat162_rn(a - hf.x, b - hf.y);
    h = *reinterpret_cast<uint32_t*>(&hh);
    l = *reinterpret_cast<uint32_t*>(&ll);
}

// smem chunk swizzle: row stride 64B (32 bf16), 4 x 16B chunks per row.
// chunk' = c ^ ((row>>1)&3) -> conflict-free ldmatrix (8-row phases hit 8 distinct
// 4-bank slots).
__device__ __forceinline__ uint32_t soff(int row, int c) {
    return (uint32_t)(row * 64 + ((c ^ ((row >> 1) & 3)) << 4));
}

// ---------------- HMMA bf16-split GEMM ----------------
// C[128,128] tile = (Ah+Al)[M,1024] @ (Bh+Bl)^T ; B stored [N][K] K-major.
// ACT: 1 = silu. WMODE: 0 = write bf16 hi/lo planes, 1 = write fp32.
template <int ACT, int WMODE>
__global__ void __launch_bounds__(256, 2)
gemm_hmma(const __nv_bfloat16* __restrict__ Ah, const __nv_bfloat16* __restrict__ Al,
          const __nv_bfloat16* __restrict__ Bh, const __nv_bfloat16* __restrict__ Bl,
          const float* __restrict__ bias,
          __nv_bfloat16* __restrict__ Ch, __nv_bfloat16* __restrict__ Cl,
          float* __restrict__ Cf) {
    __shared__ __align__(128) char smem[3 * 16384];   // stage: A 8KB + B 8KB

    const int tid = threadIdx.x, lane = tid & 31, wid = tid >> 5;
    const int bm = blockIdx.y * 128, bn = blockIdx.x * 128;
    const int wm = (wid >> 2) * 64, wn = (wid & 3) * 32;
    const uint32_t sb = (uint32_t)__cvta_generic_to_shared(smem);

    float acc[4][4][4] = {};

    auto stage_load = [&](int kt) {
        const int s = kt % 3;
        const int p = kt % 3;                       // plane (same modulus, fine)
        const int rk = (kt / 3) * 32;
        const __nv_bfloat16* Asrc = (p == 2) ? Al : Ah;
        const __nv_bfloat16* Bsrc = (p == 1) ? Bl : Bh;
        const uint32_t sA = sb + s * 16384;
        const uint32_t sB = sA + 8192;
#pragma unroll
        for (int i = 0; i < 2; i++) {
            const int idx = tid + i * 256;
            const int row = idx >> 2, c = idx & 3;
            const uint32_t off = soff(row, c);
            const __nv_bfloat16* ga = Asrc + (size_t)(bm + row) * D + rk + c * 8;
            const __nv_bfloat16* gb = Bsrc + (size_t)(bn + row) * D + rk + c * 8;
            asm volatile("cp.async.cg.shared.global [%0], [%1], 16;" :: "r"(sA + off), "l"(ga));
            asm volatile("cp.async.cg.shared.global [%0], [%1], 16;" :: "r"(sB + off), "l"(gb));
        }
        asm volatile("cp.async.commit_group;" ::: "memory");
    };

    auto compute = [&](int kt) {
        const int s = kt % 3;
        const uint32_t sA = sb + s * 16384;
        const uint32_t sB = sA + 8192;
#pragma unroll
        for (int kh = 0; kh < 2; kh++) {
            uint32_t a[4][4], b[4][2];
#pragma unroll
            for (int mf = 0; mf < 4; mf++) {
                const int row = wm + mf * 16 + (lane & 15);
                const int c = kh * 2 + (lane >> 4);
                asm volatile("ldmatrix.sync.aligned.m8n8.x4.shared.b16 {%0,%1,%2,%3}, [%4];"
                             : "=r"(a[mf][0]), "=r"(a[mf][1]), "=r"(a[mf][2]), "=r"(a[mf][3])
                             : "r"(sA + soff(row, c)));
            }
#pragma unroll
            for (int g = 0; g < 2; g++) {
                const int row = wn + g * 16 + ((lane >> 4) << 3) + (lane & 7);
                const int c = kh * 2 + ((lane >> 3) & 1);
                uint32_t r0, r1, r2, r3;
                asm volatile("ldmatrix.sync.aligned.m8n8.x4.shared.b16 {%0,%1,%2,%3}, [%4];"
                             : "=r"(r0), "=r"(r1), "=r"(r2), "=r"(r3)
                             : "r"(sB + soff(row, c)));
                b[g * 2][0] = r0; b[g * 2][1] = r1;
                b[g * 2 + 1][0] = r2; b[g * 2 + 1][1] = r3;
            }
#pragma unroll
            for (int mf = 0; mf < 4; mf++)
#pragma unroll
                for (int nf = 0; nf < 4; nf++)
                    asm volatile(
                        "mma.sync.aligned.m16n8k16.row.col.f32.bf16.bf16.f32 "
                        "{%0,%1,%2,%3}, {%4,%5,%6,%7}, {%8,%9}, {%0,%1,%2,%3};"
                        : "+f"(acc[mf][nf][0]), "+f"(acc[mf][nf][1]),
                          "+f"(acc[mf][nf][2]), "+f"(acc[mf][nf][3])
                        : "r"(a[mf][0]), "r"(a[mf][1]), "r"(a[mf][2]), "r"(a[mf][3]),
                          "r"(b[nf][0]), "r"(b[nf][1]));
        }
    };

    stage_load(0);
    stage_load(1);
    for (int kt = 0; kt < NV; kt++) {
        asm volatile("cp.async.wait_group 1;" ::: "memory");
        __syncthreads();
        if (kt + 2 < NV) stage_load(kt + 2);
        else asm volatile("cp.async.commit_group;" ::: "memory");
        compute(kt);
    }

    // ---- epilogue: bias (+silu), write fp32 or split bf16 planes ----
    float2 bias2[4];
#pragma unroll
    for (int nf = 0; nf < 4; nf++)
        bias2[nf] = __ldg((const float2*)(bias + bn + wn + nf * 8 + (lane & 3) * 2));

#pragma unroll
    for (int mf = 0; mf < 4; mf++) {
#pragma unroll
        for (int rh = 0; rh < 2; rh++) {
            const int row = bm + wm + mf * 16 + (lane >> 2) + rh * 8;
#pragma unroll
            for (int nf = 0; nf < 4; nf++) {
                const int n = bn + wn + nf * 8 + (lane & 3) * 2;
                float v0 = acc[mf][nf][rh * 2 + 0] + bias2[nf].x;
                float v1 = acc[mf][nf][rh * 2 + 1] + bias2[nf].y;
                if (ACT == 1) {
                    v0 = v0 / (1.0f + __expf(-v0));
                    v1 = v1 / (1.0f + __expf(-v1));
                }
                if (WMODE == 0) {
                    uint32_t h, l;
                    split2(v0, v1, h, l);
                    *(uint32_t*)(Ch + (size_t)row * D + n) = h;
                    *(uint32_t*)(Cl + (size_t)row * D + n) = l;
                } else {
                    *(float2*)(Cf + (size_t)row * D + n) = make_float2(v0, v1);
                }
            }
        }
    }
}

// ---------------- aux kernels ----------------
__global__ void __launch_bounds__(256) xsplit(const float2* __restrict__ x,
                                              uint32_t* __restrict__ h,
                                              uint32_t* __restrict__ l) {
    size_t i = (size_t)blockIdx.x * 256 + threadIdx.x;
    float2 v = x[i];
    uint32_t a, b;
    split2(v.x, v.y, a, b);
    h[i] = a; l[i] = b;
}

// transpose 1024x1024 weight W[k][n] -> T[n][k], split hi/lo bf16 planes
__global__ void __launch_bounds__(256) wsplit(const float* __restrict__ W,
                                              __nv_bfloat16* __restrict__ Th,
                                              __nv_bfloat16* __restrict__ Tl) {
    __shared__ float t[32][33];
    const int bx = blockIdx.x * 32, by = blockIdx.y * 32;
    const int tx = threadIdx.x, ty = threadIdx.y;
#pragma unroll
    for (int i = 0; i < 32; i += 8) t[ty + i][tx] = W[(size_t)(by + ty + i) * D + bx + tx];
    __syncthreads();
#pragma unroll
    for (int i = 0; i < 32; i += 8) {
        float v = t[tx][ty + i];
        __nv_bfloat16 hv = __float2bfloat16(v);
        size_t o = (size_t)(bx + ty + i) * D + by + tx;
        Th[o] = hv;
        Tl[o] = __float2bfloat16(v - __bfloat162float(hv));
    }
}

// LayerNorm (D=1024, eps=1e-5, no affine) fused with hi/lo split output
__global__ void __launch_bounds__(256) ln_split(const float* __restrict__ in,
                                                uint32_t* __restrict__ h,
                                                uint32_t* __restrict__ l) {
    __shared__ float2 red[8];
    const int row = blockIdx.x;
    const int tid = threadIdx.x;
    const float4 v = *(const float4*)(in + (size_t)row * D + tid * 4);
    float s = v.x + v.y + v.z + v.w;
    float ss = v.x * v.x + v.y * v.y + v.z * v.z + v.w * v.w;
#pragma unroll
    for (int o = 16; o > 0; o >>= 1) {
        s += __shfl_xor_sync(0xFFFFFFFFu, s, o);
        ss += __shfl_xor_sync(0xFFFFFFFFu, ss, o);
    }
    if ((tid & 31) == 0) red[tid >> 5] = make_float2(s, ss);
    __syncthreads();
    if (tid < 32) {
        float2 r0 = (tid < 8) ? red[tid] : make_float2(0.f, 0.f);
        s = r0.x; ss = r0.y;
#pragma unroll
        for (int o = 4; o > 0; o >>= 1) {
            s += __shfl_xor_sync(0xFFFFFFFFu, s, o);
            ss += __shfl_xor_sync(0xFFFFFFFFu, ss, o);
        }
        if (tid == 0) red[0] = make_float2(s, ss);
    }
    __syncthreads();
    const float mu = red[0].x * (1.0f / D);
    const float var = red[0].y * (1.0f / D) - mu * mu;
    const float r = rsqrtf(var + 1e-5f);
    uint2 ho, lo;
    split2((v.x - mu) * r, (v.y - mu) * r, ho.x, lo.x);
    split2((v.z - mu) * r, (v.w - mu) * r, ho.y, lo.y);
    *(uint2*)&h[(size_t)row * (D / 2) + tid * 2] = ho;
    *(uint2*)&l[(size_t)row * (D / 2) + tid * 2] = lo;
}

// ---------------- launch ----------------
extern "C" void kernel_launch(void* const* d_in, const int* in_sizes, int n_in,
                              void* d_out, int out_size) {
    const float* x     = (const float*)d_in[0];
    const float* wq    = (const float*)d_in[1];
    const float* bq    = (const float*)d_in[2];
    const float* mlp_w = (const float*)d_in[3];
    const float* mlp_b = (const float*)d_in[4];
    const float* w_out = (const float*)d_in[5];
    const float* b_out = (const float*)d_in[6];
    float* out = (float*)d_out;
    const int M = in_sizes[0] / D;   // 16384

    __nv_bfloat16 *ah, *al, *bh, *bl, *wh, *wl;
    float* q;
    cudaGetSymbolAddress((void**)&ah, g_ah);
    cudaGetSymbolAddress((void**)&al, g_al);
    cudaGetSymbolAddress((void**)&bh, g_bh);
    cudaGetSymbolAddress((void**)&bl, g_bl);
    cudaGetSymbolAddress((void**)&wh, g_wh);
    cudaGetSymbolAddress((void**)&wl, g_wl);
    cudaGetSymbolAddress((void**)&q, g_q);

    dim3 wg(D / 32, D / 32), wb(32, 8);
    wsplit<<<wg, wb>>>(wq, wh, wl);
    for (int i = 0; i < 4; i++)
        wsplit<<<wg, wb>>>(mlp_w + (size_t)i * DD, wh + (size_t)(1 + i) * DD, wl + (size_t)(1 + i) * DD);
    wsplit<<<wg, wb>>>(w_out, wh + 5ull * DD, wl + 5ull * DD);

    xsplit<<<(M * D) / 512, 256>>>((const float2*)x, (uint32_t*)ah, (uint32_t*)al);

    dim3 gg(D / 128, M / 128);
    dim3 bb(256);
    // q = x @ wq + bq (fp32 out)
    gemm_hmma<0, 1><<<gg, bb>>>(ah, al, wh, wl, bq, nullptr, nullptr, q);
    // q_norm = LN(q) -> hi/lo planes
    ln_split<<<M, 256>>>(q, (uint32_t*)bh, (uint32_t*)bl);
    // memory MLP: 3x (GEMM+SiLU), final GEMM no act
    gemm_hmma<1, 0><<<gg, bb>>>(bh, bl, wh + 1ull * DD, wl + 1ull * DD, mlp_b + 0 * D, ah, al, nullptr);
    gemm_hmma<1, 0><<<gg, bb>>>(ah, al, wh + 2ull * DD, wl + 2ull * DD, mlp_b + 1 * D, bh, bl, nullptr);
    gemm_hmma<1, 0><<<gg, bb>>>(bh, bl, wh + 3ull * DD, wl + 3ull * DD, mlp_b + 2 * D, ah, al, nullptr);
    gemm_hmma<0, 0><<<gg, bb>>>(ah, al, wh + 4ull * DD, wl + 4ull * DD, mlp_b + 3 * D, bh, bl, nullptr);
    // out = h @ w_out + b_out (straight-through term is 0 in forward)
    gemm_hmma<0, 1><<<gg, bb>>>(bh, bl, wh + 5ull * DD, wl + 5ull * DD, b_out, nullptr, nullptr, out);
}

// round 5
// speedup vs baseline: 3.1312x; 1.2205x over previous
#include <cuda_runtime.h>
#include <cuda_bf16.h>
#include <cstdint>

#define D 1024
#define MAXR 16384
#define DD (D * D)
#define NRC 32                 // real K chunks of 32
#define STAGE 32768            // Ah 8K | Al 8K | Bh 8K | Bl 8K
#define SMEM_SZ (3 * STAGE)    // 96 KB

// ---------------- device scratch (allocation-free rule) ----------------
__device__ __align__(256) __nv_bfloat16 g_ah[MAXR * D], g_al[MAXR * D];
__device__ __align__(256) __nv_bfloat16 g_bh[MAXR * D], g_bl[MAXR * D];
__device__ __align__(256) float g_q[MAXR * D];
__device__ __align__(256) __nv_bfloat16 g_wh[6 * DD], g_wl[6 * DD];

__device__ __forceinline__ void split2(float a, float b, uint32_t& h, uint32_t& l) {
    __nv_bfloat162 hh = __floats2bfloat162_rn(a, b);
    float2 hf = __bfloat1622float2(hh);
    __nv_bfloat162 ll = __floats2bfloat162_rn(a - hf.x, b - hf.y);
    h = *reinterpret_cast<uint32_t*>(&hh);
    l = *reinterpret_cast<uint32_t*>(&ll);
}

// smem swizzle: row stride 64B (32 bf16), 4 x 16B chunks per row
__device__ __forceinline__ uint32_t soff(int row, int c) {
    return (uint32_t)(row * 64 + ((c ^ ((row >> 1) & 3)) << 4));
}

#define LDSM4(r0, r1, r2, r3, addr)                                                \
    asm volatile("ldmatrix.sync.aligned.m8n8.x4.shared.b16 {%0,%1,%2,%3}, [%4];"   \
                 : "=r"(r0), "=r"(r1), "=r"(r2), "=r"(r3) : "r"(addr))

#define MMA16816(ac, af, bf)                                                       \
    asm volatile("mma.sync.aligned.m16n8k16.row.col.f32.bf16.bf16.f32 "            \
                 "{%0,%1,%2,%3}, {%4,%5,%6,%7}, {%8,%9}, {%0,%1,%2,%3};"           \
                 : "+f"((ac)[0]), "+f"((ac)[1]), "+f"((ac)[2]), "+f"((ac)[3])      \
                 : "r"((af)[0]), "r"((af)[1]), "r"((af)[2]), "r"((af)[3]),         \
                   "r"((bf)[0]), "r"((bf)[1]))

// ---------------- HMMA bf16-split GEMM, plane-dedup mainloop ----------------
// C = (Ah+Al) @ (Bh+Bl)^T : products hh + hl + lh, fp32 accum.
// ACT: 1 = silu. WMODE: 0 = write bf16 hi/lo planes, 1 = write fp32.
template <int ACT, int WMODE>
__global__ void __launch_bounds__(256, 2)
gemm_hmma(const __nv_bfloat16* __restrict__ Ah, const __nv_bfloat16* __restrict__ Al,
          const __nv_bfloat16* __restrict__ Bh, const __nv_bfloat16* __restrict__ Bl,
          const float* __restrict__ bias,
          __nv_bfloat16* __restrict__ Ch, __nv_bfloat16* __restrict__ Cl,
          float* __restrict__ Cf) {
    extern __shared__ __align__(128) char smem[];
    const int tid = threadIdx.x, lane = tid & 31, wid = tid >> 5;
    const int bm = blockIdx.y * 128, bn = blockIdx.x * 128;
    const int wm = (wid >> 2) * 64, wn = (wid & 3) * 32;
    const uint32_t sb = (uint32_t)__cvta_generic_to_shared(smem);

    float acc[4][4][4] = {};

    auto stage_load = [&](int kt) {
        const uint32_t st = sb + (uint32_t)(kt % 3) * STAGE;
        const int rk = kt * 32;
#pragma unroll
        for (int i = 0; i < 2; i++) {
            const int idx = tid + i * 256;
            const int row = idx >> 2, c = idx & 3;
            const uint32_t off = soff(row, c);
            const size_t ga = (size_t)(bm + row) * D + rk + c * 8;
            const size_t gb = (size_t)(bn + row) * D + rk + c * 8;
            asm volatile("cp.async.cg.shared.global [%0], [%1], 16;" :: "r"(st + off),         "l"(Ah + ga));
            asm volatile("cp.async.cg.shared.global [%0], [%1], 16;" :: "r"(st + 8192 + off),  "l"(Al + ga));
            asm volatile("cp.async.cg.shared.global [%0], [%1], 16;" :: "r"(st + 16384 + off), "l"(Bh + gb));
            asm volatile("cp.async.cg.shared.global [%0], [%1], 16;" :: "r"(st + 24576 + off), "l"(Bl + gb));
        }
        asm volatile("cp.async.commit_group;" ::: "memory");
    };

    auto compute = [&](int kt) {
        const uint32_t st = sb + (uint32_t)(kt % 3) * STAGE;
#pragma unroll
        for (int kh = 0; kh < 2; kh++) {
            const int ar = wm + (lane & 15);
            const int ac_ = kh * 2 + (lane >> 4);
            const int br = wn + ((lane >> 4) << 3) + (lane & 7);
            const int bc = kh * 2 + ((lane >> 3) & 1);

            uint32_t af[4][4], bh_[4][2], bl_[4][2];
            // A-hi fragments
#pragma unroll
            for (int mf = 0; mf < 4; mf++)
                LDSM4(af[mf][0], af[mf][1], af[mf][2], af[mf][3],
                      st + soff(ar + mf * 16, ac_));
            // B-hi fragments (4 nf frags via 2 x4 loads)
#pragma unroll
            for (int g = 0; g < 2; g++) {
                uint32_t r0, r1, r2, r3;
                LDSM4(r0, r1, r2, r3, st + 16384 + soff(br + g * 16, bc));
                bh_[g * 2][0] = r0; bh_[g * 2][1] = r1;
                bh_[g * 2 + 1][0] = r2; bh_[g * 2 + 1][1] = r3;
            }
            // B-lo fragments
#pragma unroll
            for (int g = 0; g < 2; g++) {
                uint32_t r0, r1, r2, r3;
                LDSM4(r0, r1, r2, r3, st + 24576 + soff(br + g * 16, bc));
                bl_[g * 2][0] = r0; bl_[g * 2][1] = r1;
                bl_[g * 2 + 1][0] = r2; bl_[g * 2 + 1][1] = r3;
            }
            // hh + hl products (Ah reused)
#pragma unroll
            for (int mf = 0; mf < 4; mf++)
#pragma unroll
                for (int nf = 0; nf < 4; nf++) {
                    MMA16816(acc[mf][nf], af[mf], bh_[nf]);
                    MMA16816(acc[mf][nf], af[mf], bl_[nf]);
                }
            // A-lo fragments (overwrite af) then lh product (Bh reused)
#pragma unroll
            for (int mf = 0; mf < 4; mf++)
                LDSM4(af[mf][0], af[mf][1], af[mf][2], af[mf][3],
                      st + 8192 + soff(ar + mf * 16, ac_));
#pragma unroll
            for (int mf = 0; mf < 4; mf++)
#pragma unroll
                for (int nf = 0; nf < 4; nf++)
                    MMA16816(acc[mf][nf], af[mf], bh_[nf]);
        }
    };

    stage_load(0);
    stage_load(1);
    for (int kt = 0; kt < NRC; kt++) {
        asm volatile("cp.async.wait_group 1;" ::: "memory");
        __syncthreads();
        if (kt + 2 < NRC) stage_load(kt + 2);
        else asm volatile("cp.async.commit_group;" ::: "memory");
        compute(kt);
    }

    // ---- epilogue: bias (+silu), write fp32 or split bf16 planes ----
    float2 bias2[4];
#pragma unroll
    for (int nf = 0; nf < 4; nf++)
        bias2[nf] = __ldg((const float2*)(bias + bn + wn + nf * 8 + (lane & 3) * 2));

#pragma unroll
    for (int mf = 0; mf < 4; mf++) {
#pragma unroll
        for (int rh = 0; rh < 2; rh++) {
            const int row = bm + wm + mf * 16 + (lane >> 2) + rh * 8;
#pragma unroll
            for (int nf = 0; nf < 4; nf++) {
                const int n = bn + wn + nf * 8 + (lane & 3) * 2;
                float v0 = acc[mf][nf][rh * 2 + 0] + bias2[nf].x;
                float v1 = acc[mf][nf][rh * 2 + 1] + bias2[nf].y;
                if (ACT == 1) {
                    v0 = v0 / (1.0f + __expf(-v0));
                    v1 = v1 / (1.0f + __expf(-v1));
                }
                if (WMODE == 0) {
                    uint32_t h, l;
                    split2(v0, v1, h, l);
                    *(uint32_t*)(Ch + (size_t)row * D + n) = h;
                    *(uint32_t*)(Cl + (size_t)row * D + n) = l;
                } else {
                    *(float2*)(Cf + (size_t)row * D + n) = make_float2(v0, v1);
                }
            }
        }
    }
}

// ---------------- aux kernels ----------------
__global__ void __launch_bounds__(256) xsplit(const float2* __restrict__ x,
                                              uint32_t* __restrict__ h,
                                              uint32_t* __restrict__ l) {
    size_t i = (size_t)blockIdx.x * 256 + threadIdx.x;
    float2 v = x[i];
    uint32_t a, b;
    split2(v.x, v.y, a, b);
    h[i] = a; l[i] = b;
}

// transpose 1024x1024 weight W[k][n] -> T[n][k], split hi/lo bf16 planes
__global__ void __launch_bounds__(256) wsplit(const float* __restrict__ W,
                                              __nv_bfloat16* __restrict__ Th,
                                              __nv_bfloat16* __restrict__ Tl) {
    __shared__ float t[32][33];
    const int bx = blockIdx.x * 32, by = blockIdx.y * 32;
    const int tx = threadIdx.x, ty = threadIdx.y;
#pragma unroll
    for (int i = 0; i < 32; i += 8) t[ty + i][tx] = W[(size_t)(by + ty + i) * D + bx + tx];
    __syncthreads();
#pragma unroll
    for (int i = 0; i < 32; i += 8) {
        float v = t[tx][ty + i];
        __nv_bfloat16 hv = __float2bfloat16(v);
        size_t o = (size_t)(bx + ty + i) * D + by + tx;
        Th[o] = hv;
        Tl[o] = __float2bfloat16(v - __bfloat162float(hv));
    }
}

// LayerNorm (D=1024, eps=1e-5, no affine) fused with hi/lo split output
__global__ void __launch_bounds__(256) ln_split(const float* __restrict__ in,
                                                uint32_t* __restrict__ h,
                                                uint32_t* __restrict__ l) {
    __shared__ float2 red[8];
    const int row = blockIdx.x;
    const int tid = threadIdx.x;
    const float4 v = *(const float4*)(in + (size_t)row * D + tid * 4);
    float s = v.x + v.y + v.z + v.w;
    float ss = v.x * v.x + v.y * v.y + v.z * v.z + v.w * v.w;
#pragma unroll
    for (int o = 16; o > 0; o >>= 1) {
        s += __shfl_xor_sync(0xFFFFFFFFu, s, o);
        ss += __shfl_xor_sync(0xFFFFFFFFu, ss, o);
    }
    if ((tid & 31) == 0) red[tid >> 5] = make_float2(s, ss);
    __syncthreads();
    if (tid < 32) {
        float2 r0 = (tid < 8) ? red[tid] : make_float2(0.f, 0.f);
        s = r0.x; ss = r0.y;
#pragma unroll
        for (int o = 4; o > 0; o >>= 1) {
            s += __shfl_xor_sync(0xFFFFFFFFu, s, o);
            ss += __shfl_xor_sync(0xFFFFFFFFu, ss, o);
        }
        if (tid == 0) red[0] = make_float2(s, ss);
    }
    __syncthreads();
    const float mu = red[0].x * (1.0f / D);
    const float var = red[0].y * (1.0f / D) - mu * mu;
    const float r = rsqrtf(var + 1e-5f);
    uint2 ho, lo;
    split2((v.x - mu) * r, (v.y - mu) * r, ho.x, lo.x);
    split2((v.z - mu) * r, (v.w - mu) * r, ho.y, lo.y);
    *(uint2*)&h[(size_t)row * (D / 2) + tid * 2] = ho;
    *(uint2*)&l[(size_t)row * (D / 2) + tid * 2] = lo;
}

// ---------------- launch ----------------
extern "C" void kernel_launch(void* const* d_in, const int* in_sizes, int n_in,
                              void* d_out, int out_size) {
    const float* x     = (const float*)d_in[0];
    const float* wq    = (const float*)d_in[1];
    const float* bq    = (const float*)d_in[2];
    const float* mlp_w = (const float*)d_in[3];
    const float* mlp_b = (const float*)d_in[4];
    const float* w_out = (const float*)d_in[5];
    const float* b_out = (const float*)d_in[6];
    float* out = (float*)d_out;
    const int M = in_sizes[0] / D;   // 16384

    __nv_bfloat16 *ah, *al, *bh, *bl, *wh, *wl;
    float* q;
    cudaGetSymbolAddress((void**)&ah, g_ah);
    cudaGetSymbolAddress((void**)&al, g_al);
    cudaGetSymbolAddress((void**)&bh, g_bh);
    cudaGetSymbolAddress((void**)&bl, g_bl);
    cudaGetSymbolAddress((void**)&wh, g_wh);
    cudaGetSymbolAddress((void**)&wl, g_wl);
    cudaGetSymbolAddress((void**)&q, g_q);

    cudaFuncSetAttribute(gemm_hmma<0, 1>, cudaFuncAttributeMaxDynamicSharedMemorySize, SMEM_SZ);
    cudaFuncSetAttribute(gemm_hmma<1, 0>, cudaFuncAttributeMaxDynamicSharedMemorySize, SMEM_SZ);
    cudaFuncSetAttribute(gemm_hmma<0, 0>, cudaFuncAttributeMaxDynamicSharedMemorySize, SMEM_SZ);

    dim3 wg(D / 32, D / 32), wb(32, 8);
    wsplit<<<wg, wb>>>(wq, wh, wl);
    for (int i = 0; i < 4; i++)
        wsplit<<<wg, wb>>>(mlp_w + (size_t)i * DD, wh + (size_t)(1 + i) * DD, wl + (size_t)(1 + i) * DD);
    wsplit<<<wg, wb>>>(w_out, wh + 5ull * DD, wl + 5ull * DD);

    xsplit<<<(M * D) / 512, 256>>>((const float2*)x, (uint32_t*)ah, (uint32_t*)al);

    dim3 gg(D / 128, M / 128);
    dim3 bb(256);
    // q = x @ wq + bq (fp32 out)
    gemm_hmma<0, 1><<<gg, bb, SMEM_SZ>>>(ah, al, wh, wl, bq, nullptr, nullptr, q);
    // q_norm = LN(q) -> hi/lo planes
    ln_split<<<M, 256>>>(q, (uint32_t*)bh, (uint32_t*)bl);
    // memory MLP: 3x (GEMM+SiLU), final GEMM no act
    gemm_hmma<1, 0><<<gg, bb, SMEM_SZ>>>(bh, bl, wh + 1ull * DD, wl + 1ull * DD, mlp_b + 0 * D, ah, al, nullptr);
    gemm_hmma<1, 0><<<gg, bb, SMEM_SZ>>>(ah, al, wh + 2ull * DD, wl + 2ull * DD, mlp_b + 1 * D, bh, bl, nullptr);
    gemm_hmma<1, 0><<<gg, bb, SMEM_SZ>>>(bh, bl, wh + 3ull * DD, wl + 3ull * DD, mlp_b + 2 * D, ah, al, nullptr);
    gemm_hmma<0, 0><<<gg, bb, SMEM_SZ>>>(ah, al, wh + 4ull * DD, wl + 4ull * DD, mlp_b + 3 * D, bh, bl, nullptr);
    // out = h @ w_out + b_out (straight-through term is 0 in forward)
    gemm_hmma<0, 1><<<gg, bb, SMEM_SZ>>>(bh, bl, wh + 5ull * DD, wl + 5ull * DD, b_out, nullptr, nullptr, out);
}

// round 6
// speedup vs baseline: 3.3432x; 1.0677x over previous
#include <cuda_runtime.h>
#include <cuda_bf16.h>
#include <cstdint>

#define D 1024
#define MAXR 16384
#define DD (D * D)
#define NRC 32                 // real K chunks of 32
#define STAGE 32768            // Ah 8K | Al 8K | Bh 8K | Bl 8K
#define NSTG 4
#define SMEM_SZ (NSTG * STAGE) // 128 KB

// ---------------- device scratch (allocation-free rule) ----------------
__device__ __align__(256) __nv_bfloat16 g_ah[MAXR * D], g_al[MAXR * D];
__device__ __align__(256) __nv_bfloat16 g_bh[MAXR * D], g_bl[MAXR * D];
__device__ __align__(256) float g_q[MAXR * D];
__device__ __align__(256) __nv_bfloat16 g_wh[6 * DD], g_wl[6 * DD];

__device__ __forceinline__ void split2(float a, float b, uint32_t& h, uint32_t& l) {
    __nv_bfloat162 hh = __floats2bfloat162_rn(a, b);
    float2 hf = __bfloat1622float2(hh);
    __nv_bfloat162 ll = __floats2bfloat162_rn(a - hf.x, b - hf.y);
    h = *reinterpret_cast<uint32_t*>(&hh);
    l = *reinterpret_cast<uint32_t*>(&ll);
}

// smem swizzle: row stride 64B (32 bf16), 4 x 16B chunks per row
__device__ __forceinline__ uint32_t soff(int row, int c) {
    return (uint32_t)(row * 64 + ((c ^ ((row >> 1) & 3)) << 4));
}

#define LDSM4(r0, r1, r2, r3, addr)                                                \
    asm volatile("ldmatrix.sync.aligned.m8n8.x4.shared.b16 {%0,%1,%2,%3}, [%4];"   \
                 : "=r"(r0), "=r"(r1), "=r"(r2), "=r"(r3) : "r"(addr))

#define MMA16816(ac, af, bf)                                                       \
    asm volatile("mma.sync.aligned.m16n8k16.row.col.f32.bf16.bf16.f32 "            \
                 "{%0,%1,%2,%3}, {%4,%5,%6,%7}, {%8,%9}, {%0,%1,%2,%3};"           \
                 : "+f"((ac)[0]), "+f"((ac)[1]), "+f"((ac)[2]), "+f"((ac)[3])      \
                 : "r"((af)[0]), "r"((af)[1]), "r"((af)[2]), "r"((af)[3]),         \
                   "r"((bf)[0]), "r"((bf)[1]))

// ---------------- HMMA bf16-split GEMM, 1 CTA/SM, double-buffered frags ----------------
// C = (Ah+Al) @ (Bh+Bl)^T : products hh + hl + lh, fp32 accum.
// ACT: 1 = silu. WMODE: 0 = write bf16 hi/lo planes, 1 = write fp32.
template <int ACT, int WMODE>
__global__ void __launch_bounds__(256, 1)
gemm_hmma(const __nv_bfloat16* __restrict__ Ah, const __nv_bfloat16* __restrict__ Al,
          const __nv_bfloat16* __restrict__ Bh, const __nv_bfloat16* __restrict__ Bl,
          const float* __restrict__ bias,
          __nv_bfloat16* __restrict__ Ch, __nv_bfloat16* __restrict__ Cl,
          float* __restrict__ Cf) {
    extern __shared__ __align__(128) char smem[];
    const int tid = threadIdx.x, lane = tid & 31, wid = tid >> 5;
    const int bm = blockIdx.y * 128, bn = blockIdx.x * 128;
    const int wm = (wid >> 2) * 64, wn = (wid & 3) * 32;
    const uint32_t sb = (uint32_t)__cvta_generic_to_shared(smem);

    float acc[4][4][4] = {};
    uint32_t ahf[2][4][4], alf[2][4][4], bhf[2][4][2], blf[2][4][2];

    auto stage_load = [&](int kt) {
        const uint32_t st = sb + (uint32_t)(kt & (NSTG - 1)) * STAGE;
        const int rk = kt * 32;
#pragma unroll
        for (int i = 0; i < 2; i++) {
            const int idx = tid + i * 256;
            const int row = idx >> 2, c = idx & 3;
            const uint32_t off = soff(row, c);
            const size_t ga = (size_t)(bm + row) * D + rk + c * 8;
            const size_t gb = (size_t)(bn + row) * D + rk + c * 8;
            asm volatile("cp.async.cg.shared.global [%0], [%1], 16;" :: "r"(st + off),         "l"(Ah + ga));
            asm volatile("cp.async.cg.shared.global [%0], [%1], 16;" :: "r"(st + 8192 + off),  "l"(Al + ga));
            asm volatile("cp.async.cg.shared.global [%0], [%1], 16;" :: "r"(st + 16384 + off), "l"(Bh + gb));
            asm volatile("cp.async.cg.shared.global [%0], [%1], 16;" :: "r"(st + 24576 + off), "l"(Bl + gb));
        }
        asm volatile("cp.async.commit_group;" ::: "memory");
    };

    auto ldfrag = [&](int b, uint32_t st, int kh) {
        const int ar = wm + (lane & 15);
        const int ac_ = kh * 2 + (lane >> 4);
        const int br = wn + ((lane >> 4) << 3) + (lane & 7);
        const int bc = kh * 2 + ((lane >> 3) & 1);
#pragma unroll
        for (int mf = 0; mf < 4; mf++)
            LDSM4(ahf[b][mf][0], ahf[b][mf][1], ahf[b][mf][2], ahf[b][mf][3],
                  st + soff(ar + mf * 16, ac_));
#pragma unroll
        for (int mf = 0; mf < 4; mf++)
            LDSM4(alf[b][mf][0], alf[b][mf][1], alf[b][mf][2], alf[b][mf][3],
                  st + 8192 + soff(ar + mf * 16, ac_));
#pragma unroll
        for (int g = 0; g < 2; g++) {
            uint32_t r0, r1, r2, r3;
            LDSM4(r0, r1, r2, r3, st + 16384 + soff(br + g * 16, bc));
            bhf[b][g * 2][0] = r0; bhf[b][g * 2][1] = r1;
            bhf[b][g * 2 + 1][0] = r2; bhf[b][g * 2 + 1][1] = r3;
        }
#pragma unroll
        for (int g = 0; g < 2; g++) {
            uint32_t r0, r1, r2, r3;
            LDSM4(r0, r1, r2, r3, st + 24576 + soff(br + g * 16, bc));
            blf[b][g * 2][0] = r0; blf[b][g * 2][1] = r1;
            blf[b][g * 2 + 1][0] = r2; blf[b][g * 2 + 1][1] = r3;
        }
    };

    auto mma_all = [&](int b) {
#pragma unroll
        for (int mf = 0; mf < 4; mf++)
#pragma unroll
            for (int nf = 0; nf < 4; nf++)
                MMA16816(acc[mf][nf], ahf[b][mf], bhf[b][nf]);
#pragma unroll
        for (int mf = 0; mf < 4; mf++)
#pragma unroll
            for (int nf = 0; nf < 4; nf++)
                MMA16816(acc[mf][nf], ahf[b][mf], blf[b][nf]);
#pragma unroll
        for (int mf = 0; mf < 4; mf++)
#pragma unroll
            for (int nf = 0; nf < 4; nf++)
                MMA16816(acc[mf][nf], alf[b][mf], bhf[b][nf]);
    };

    stage_load(0);
    stage_load(1);
    stage_load(2);
    asm volatile("cp.async.wait_group 2;" ::: "memory");
    __syncthreads();
    ldfrag(0, sb, 0);

    for (int kt = 0; kt < NRC; kt++) {
        const uint32_t st = sb + (uint32_t)(kt & (NSTG - 1)) * STAGE;
        ldfrag(1, st, 1);            // kh=1 frags issue; latency hides under kh=0 MMAs
        mma_all(0);
        if (kt + 3 < NRC) stage_load(kt + 3);
        mma_all(1);
        asm volatile("cp.async.wait_group 2;" ::: "memory");
        __syncthreads();
        if (kt + 1 < NRC)
            ldfrag(0, sb + (uint32_t)((kt + 1) & (NSTG - 1)) * STAGE, 0);
    }

    // ---- epilogue: bias (+silu), write fp32 or split bf16 planes ----
    float2 bias2[4];
#pragma unroll
    for (int nf = 0; nf < 4; nf++)
        bias2[nf] = __ldg((const float2*)(bias + bn + wn + nf * 8 + (lane & 3) * 2));

#pragma unroll
    for (int mf = 0; mf < 4; mf++) {
#pragma unroll
        for (int rh = 0; rh < 2; rh++) {
            const int row = bm + wm + mf * 16 + (lane >> 2) + rh * 8;
#pragma unroll
            for (int nf = 0; nf < 4; nf++) {
                const int n = bn + wn + nf * 8 + (lane & 3) * 2;
                float v0 = acc[mf][nf][rh * 2 + 0] + bias2[nf].x;
                float v1 = acc[mf][nf][rh * 2 + 1] + bias2[nf].y;
                if (ACT == 1) {
                    v0 = v0 / (1.0f + __expf(-v0));
                    v1 = v1 / (1.0f + __expf(-v1));
                }
                if (WMODE == 0) {
                    uint32_t h, l;
                    split2(v0, v1, h, l);
                    *(uint32_t*)(Ch + (size_t)row * D + n) = h;
                    *(uint32_t*)(Cl + (size_t)row * D + n) = l;
                } else {
                    *(float2*)(Cf + (size_t)row * D + n) = make_float2(v0, v1);
                }
            }
        }
    }
}

// ---------------- aux kernels ----------------
__global__ void __launch_bounds__(256) xsplit(const float2* __restrict__ x,
                                              uint32_t* __restrict__ h,
                                              uint32_t* __restrict__ l) {
    size_t i = (size_t)blockIdx.x * 256 + threadIdx.x;
    float2 v = x[i];
    uint32_t a, b;
    split2(v.x, v.y, a, b);
    h[i] = a; l[i] = b;
}

// transpose 1024x1024 weight W[k][n] -> T[n][k], split hi/lo bf16 planes
__global__ void __launch_bounds__(256) wsplit(const float* __restrict__ W,
                                              __nv_bfloat16* __restrict__ Th,
                                              __nv_bfloat16* __restrict__ Tl) {
    __shared__ float t[32][33];
    const int bx = blockIdx.x * 32, by = blockIdx.y * 32;
    const int tx = threadIdx.x, ty = threadIdx.y;
#pragma unroll
    for (int i = 0; i < 32; i += 8) t[ty + i][tx] = W[(size_t)(by + ty + i) * D + bx + tx];
    __syncthreads();
#pragma unroll
    for (int i = 0; i < 32; i += 8) {
        float v = t[tx][ty + i];
        __nv_bfloat16 hv = __float2bfloat16(v);
        size_t o = (size_t)(bx + ty + i) * D + by + tx;
        Th[o] = hv;
        Tl[o] = __float2bfloat16(v - __bfloat162float(hv));
    }
}

// LayerNorm (D=1024, eps=1e-5, no affine) fused with hi/lo split output
__global__ void __launch_bounds__(256) ln_split(const float* __restrict__ in,
                                                uint32_t* __restrict__ h,
                                                uint32_t* __restrict__ l) {
    __shared__ float2 red[8];
    const int row = blockIdx.x;
    const int tid = threadIdx.x;
    const float4 v = *(const float4*)(in + (size_t)row * D + tid * 4);
    float s = v.x + v.y + v.z + v.w;
    float ss = v.x * v.x + v.y * v.y + v.z * v.z + v.w * v.w;
#pragma unroll
    for (int o = 16; o > 0; o >>= 1) {
        s += __shfl_xor_sync(0xFFFFFFFFu, s, o);
        ss += __shfl_xor_sync(0xFFFFFFFFu, ss, o);
    }
    if ((tid & 31) == 0) red[tid >> 5] = make_float2(s, ss);
    __syncthreads();
    if (tid < 32) {
        float2 r0 = (tid < 8) ? red[tid] : make_float2(0.f, 0.f);
        s = r0.x; ss = r0.y;
#pragma unroll
        for (int o = 4; o > 0; o >>= 1) {
            s += __shfl_xor_sync(0xFFFFFFFFu, s, o);
            ss += __shfl_xor_sync(0xFFFFFFFFu, ss, o);
        }
        if (tid == 0) red[0] = make_float2(s, ss);
    }
    __syncthreads();
    const float mu = red[0].x * (1.0f / D);
    const float var = red[0].y * (1.0f / D) - mu * mu;
    const float r = rsqrtf(var + 1e-5f);
    uint2 ho, lo;
    split2((v.x - mu) * r, (v.y - mu) * r, ho.x, lo.x);
    split2((v.z - mu) * r, (v.w - mu) * r, ho.y, lo.y);
    *(uint2*)&h[(size_t)row * (D / 2) + tid * 2] = ho;
    *(uint2*)&l[(size_t)row * (D / 2) + tid * 2] = lo;
}

// ---------------- launch ----------------
extern "C" void kernel_launch(void* const* d_in, const int* in_sizes, int n_in,
                              void* d_out, int out_size) {
    const float* x     = (const float*)d_in[0];
    const float* wq    = (const float*)d_in[1];
    const float* bq    = (const float*)d_in[2];
    const float* mlp_w = (const float*)d_in[3];
    const float* mlp_b = (const float*)d_in[4];
    const float* w_out = (const float*)d_in[5];
    const float* b_out = (const float*)d_in[6];
    float* out = (float*)d_out;
    const int M = in_sizes[0] / D;   // 16384

    __nv_bfloat16 *ah, *al, *bh, *bl, *wh, *wl;
    float* q;
    cudaGetSymbolAddress((void**)&ah, g_ah);
    cudaGetSymbolAddress((void**)&al, g_al);
    cudaGetSymbolAddress((void**)&bh, g_bh);
    cudaGetSymbolAddress((void**)&bl, g_bl);
    cudaGetSymbolAddress((void**)&wh, g_wh);
    cudaGetSymbolAddress((void**)&wl, g_wl);
    cudaGetSymbolAddress((void**)&q, g_q);

    cudaFuncSetAttribute(gemm_hmma<0, 1>, cudaFuncAttributeMaxDynamicSharedMemorySize, SMEM_SZ);
    cudaFuncSetAttribute(gemm_hmma<1, 0>, cudaFuncAttributeMaxDynamicSharedMemorySize, SMEM_SZ);
    cudaFuncSetAttribute(gemm_hmma<0, 0>, cudaFuncAttributeMaxDynamicSharedMemorySize, SMEM_SZ);

    dim3 wg(D / 32, D / 32), wb(32, 8);
    wsplit<<<wg, wb>>>(wq, wh, wl);
    for (int i = 0; i < 4; i++)
        wsplit<<<wg, wb>>>(mlp_w + (size_t)i * DD, wh + (size_t)(1 + i) * DD, wl + (size_t)(1 + i) * DD);
    wsplit<<<wg, wb>>>(w_out, wh + 5ull * DD, wl + 5ull * DD);

    xsplit<<<(M * D) / 512, 256>>>((const float2*)x, (uint32_t*)ah, (uint32_t*)al);

    dim3 gg(D / 128, M / 128);
    dim3 bb(256);
    // q = x @ wq + bq (fp32 out)
    gemm_hmma<0, 1><<<gg, bb, SMEM_SZ>>>(ah, al, wh, wl, bq, nullptr, nullptr, q);
    // q_norm = LN(q) -> hi/lo planes
    ln_split<<<M, 256>>>(q, (uint32_t*)bh, (uint32_t*)bl);
    // memory MLP: 3x (GEMM+SiLU), final GEMM no act
    gemm_hmma<1, 0><<<gg, bb, SMEM_SZ>>>(bh, bl, wh + 1ull * DD, wl + 1ull * DD, mlp_b + 0 * D, ah, al, nullptr);
    gemm_hmma<1, 0><<<gg, bb, SMEM_SZ>>>(ah, al, wh + 2ull * DD, wl + 2ull * DD, mlp_b + 1 * D, bh, bl, nullptr);
    gemm_hmma<1, 0><<<gg, bb, SMEM_SZ>>>(bh, bl, wh + 3ull * DD, wl + 3ull * DD, mlp_b + 2 * D, ah, al, nullptr);
    gemm_hmma<0, 0><<<gg, bb, SMEM_SZ>>>(ah, al, wh + 4ull * DD, wl + 4ull * DD, mlp_b + 3 * D, bh, bl, nullptr);
    // out = h @ w_out + b_out (straight-through term is 0 in forward)
    gemm_hmma<0, 1><<<gg, bb, SMEM_SZ>>>(bh, bl, wh + 5ull * DD, wl + 5ull * DD, b_out, nullptr, nullptr, out);
}